// round 17
// baseline (speedup 1.0000x reference)
#include <cuda_runtime.h>
#include <cuda_bf16.h>
#include <cstdint>

#define BB 8
#define HH 192
#define WW 320
#define HW (HH*WW)
#define UPH (HH/2)
#define UPW (WW/2)

// ---------------- scratch ----------------
__device__ float    g_biflow[BB*4*HW];
__device__ float    g_accA[BB*33*HW];
__device__ float    g_accB[BB*33*HW];
__device__ float    g_warp0[BB*32*HW];
__device__ float    g_warp1[BB*32*HW];
// pixel-record tensors: [b][px][pair-word], hi/lo separate
__device__ unsigned g_R1h[16*HW*80], g_R1l[16*HW*80];     // conv1 input (80-word records)
__device__ unsigned g_h1h[16*HW*32], g_h1l[16*HW*32];     // 64ch (32w) or 32ch (16w)
__device__ unsigned g_h2h[16*HW*32], g_h2l[16*HW*32];
__device__ unsigned g_h6h[16*HW*8],  g_h6l[16*HW*8];      // 16ch (8w)
__device__ __align__(16) __nv_bfloat16 g_wprep[460800];

// ---------------- helpers ----------------
__device__ __forceinline__ uint32_t smem_u32(const void* p) {
    uint32_t a;
    asm("{ .reg .u64 t; cvta.to.shared.u64 t, %1; cvt.u32.u64 %0, t; }" : "=r"(a) : "l"(p));
    return a;
}
__device__ __forceinline__ void cp16z(uint32_t dst, const void* src, int sz) {
    asm volatile("cp.async.cg.shared.global [%0], [%1], 16, %2;" :: "r"(dst), "l"(src), "r"(sz) : "memory");
}
__device__ __forceinline__ void cp16(uint32_t dst, const void* src) {
    asm volatile("cp.async.cg.shared.global [%0], [%1], 16;" :: "r"(dst), "l"(src) : "memory");
}
#define CP_COMMIT() asm volatile("cp.async.commit_group;" ::: "memory")
#define CP_WAIT0()  asm volatile("cp.async.wait_group 0;" ::: "memory")

__device__ __forceinline__ void ldmatrix_x4(unsigned* r, uint32_t addr) {
    asm volatile("ldmatrix.sync.aligned.m8n8.x4.shared.b16 {%0,%1,%2,%3}, [%4];"
        : "=r"(r[0]), "=r"(r[1]), "=r"(r[2]), "=r"(r[3]) : "r"(addr));
}
__device__ __forceinline__ void mma16816(float* d, const unsigned* a, unsigned b0, unsigned b1) {
    asm volatile(
        "mma.sync.aligned.m16n8k16.row.col.f32.bf16.bf16.f32 "
        "{%0,%1,%2,%3}, {%4,%5,%6,%7}, {%8,%9}, {%0,%1,%2,%3};"
        : "+f"(d[0]), "+f"(d[1]), "+f"(d[2]), "+f"(d[3])
        : "r"(a[0]), "r"(a[1]), "r"(a[2]), "r"(a[3]), "r"(b0), "r"(b1));
}
__device__ __forceinline__ unsigned bf16hi_bits(float v) {
    return (unsigned)__bfloat16_as_ushort(__float2bfloat16(v));
}
__device__ __forceinline__ void pack_pair(float v0, float v1, unsigned& hp, unsigned& lp) {
    unsigned h0 = bf16hi_bits(v0);
    float r0 = v0 - __uint_as_float(h0 << 16);
    unsigned l0 = bf16hi_bits(r0);
    unsigned h1 = bf16hi_bits(v1);
    float r1 = v1 - __uint_as_float(h1 << 16);
    unsigned l1 = bf16hi_bits(r1);
    hp = h0 | (h1 << 16);
    lp = l0 | (l1 << 16);
}

// ---------------- front-end ----------------
__global__ void upsample_kernel(const float* __restrict__ src, float* __restrict__ dst) {
    int idx = blockIdx.x * 256 + threadIdx.x;
    if (idx >= BB * 4 * HW) return;
    int x = idx % WW, y = (idx / WW) % HH, bc = idx / HW;
    float sx = fminf(fmaxf(0.5f * x - 0.25f, 0.f), (float)(UPW - 1));
    float sy = fminf(fmaxf(0.5f * y - 0.25f, 0.f), (float)(UPH - 1));
    int x0 = (int)floorf(sx), y0 = (int)floorf(sy);
    float fx = sx - x0, fy = sy - y0;
    int x1 = min(x0 + 1, UPW - 1), y1 = min(y0 + 1, UPH - 1);
    const float* p = src + (size_t)bc * (UPH * UPW);
    float v = (1.f - fy) * ((1.f - fx) * p[y0 * UPW + x0] + fx * p[y0 * UPW + x1])
            +          fy * ((1.f - fx) * p[y1 * UPW + x0] + fx * p[y1 * UPW + x1]);
    dst[idx] = 2.0f * v;
}
__global__ void zero2_kernel(float* a, float* b, int n) {
    int i = blockIdx.x * 256 + threadIdx.x;
    if (i < n) { a[i] = 0.f; b[i] = 0.f; }
}
__global__ void splatM_kernel(const float* __restrict__ f0, const float* __restrict__ f1,
                              const float* __restrict__ flow4,
                              float* __restrict__ accA, float* __restrict__ accB) {
    int idx = blockIdx.x * 256 + threadIdx.x;
    if (idx >= BB * HW) return;
    int br = blockIdx.y;
    const float* feat = br ? f1 : f0;
    float* acc = br ? accB : accA;
    int fcoff = br ? 2 : 0;
    int x = idx % WW, y = (idx / WW) % HH, b = idx / HW;
    const float* fl = flow4 + ((size_t)b * 4 + fcoff) * HW + y * WW + x;
    float fx = x + fl[0], fy = y + fl[(size_t)HW];
    float x0f = floorf(fx), y0f = floorf(fy);
    float wx1 = fx - x0f, wy1 = fy - y0f, wx0 = 1.f - wx1, wy0 = 1.f - wy1;
    int ix0 = (int)x0f, iy0 = (int)y0f;
    int ixs[4] = {ix0, ix0 + 1, ix0, ix0 + 1};
    int iys[4] = {iy0, iy0, iy0 + 1, iy0 + 1};
    float ws[4] = {wx0 * wy0, wx1 * wy0, wx0 * wy1, wx1 * wy1};
    const float* fp = feat + (size_t)b * 32 * HW + y * WW + x;
    float* ap = acc + (size_t)b * 33 * HW;
    #pragma unroll
    for (int k = 0; k < 4; ++k) {
        int ix = ixs[k], iy = iys[k];
        if (ix < 0 || ix >= WW || iy < 0 || iy >= HH) continue;
        int off = iy * WW + ix;
        #pragma unroll
        for (int c = 0; c < 32; ++c)
            atomicAdd(ap + (size_t)c * HW + off, fp[(size_t)c * HW] * ws[k]);
        atomicAdd(ap + (size_t)32 * HW + off, ws[k]);
    }
}
// norm: acc -> fp32 warp planes + record words 0..15
__global__ void normM_kernel(const float* __restrict__ accA, const float* __restrict__ accB,
                             float* __restrict__ w0, float* __restrict__ w1,
                             unsigned* __restrict__ Rh, unsigned* __restrict__ Rl) {
    int idx = blockIdx.x * 256 + threadIdx.x;
    if (idx >= BB * HW) return;
    int br = blockIdx.y;
    const float* acc = br ? accB : accA;
    float* warp = br ? w1 : w0;
    int px = idx % HW, bi = idx / HW;
    float n = acc[((size_t)bi * 33 + 32) * HW + px];
    n = (n == 0.f) ? 1.f : n;
    uint4 hv[4], lv[4];
    unsigned* hw = (unsigned*)hv;
    unsigned* lw = (unsigned*)lv;
    #pragma unroll
    for (int pc = 0; pc < 16; ++pc) {
        float v0 = acc[((size_t)bi * 33 + 2 * pc) * HW + px] / n;
        float v1 = acc[((size_t)bi * 33 + 2 * pc + 1) * HW + px] / n;
        warp[((size_t)bi * 32 + 2 * pc) * HW + px] = v0;
        warp[((size_t)bi * 32 + 2 * pc + 1) * HW + px] = v1;
        pack_pair(v0, v1, hw[pc], lw[pc]);
    }
    size_t rb = ((size_t)(br * 8 + bi) * HW + px) * 80;
    #pragma unroll
    for (int q = 0; q < 4; ++q) {
        *(uint4*)(Rh + rb + q * 4) = hv[q];
        *(uint4*)(Rl + rb + q * 4) = lv[q];
    }
}
// temporal features -> record words 16..31
__global__ void packM_kernel(const float* __restrict__ ft, const float* __restrict__ bt,
                             unsigned* __restrict__ Rh, unsigned* __restrict__ Rl) {
    int idx = blockIdx.x * 256 + threadIdx.x;
    if (idx >= BB * HW) return;
    int br = blockIdx.y;
    const float* src = br ? bt : ft;
    int px = idx % HW, bi = idx / HW;
    uint4 hv[4], lv[4];
    unsigned* hw = (unsigned*)hv;
    unsigned* lw = (unsigned*)lv;
    #pragma unroll
    for (int pc = 0; pc < 16; ++pc) {
        float v0 = src[((size_t)bi * 32 + 2 * pc) * HW + px];
        float v1 = src[((size_t)bi * 32 + 2 * pc + 1) * HW + px];
        pack_pair(v0, v1, hw[pc], lw[pc]);
    }
    size_t rb = ((size_t)(br * 8 + bi) * HW + px) * 80 + 16;
    #pragma unroll
    for (int q = 0; q < 4; ++q) {
        *(uint4*)(Rh + rb + q * 4) = hv[q];
        *(uint4*)(Rl + rb + q * 4) = lv[q];
    }
}
// correlation -> record words 32..79 (41 pairs + zero pad), duplicated to both branches
__global__ void __launch_bounds__(256)
corr_kernel(const float* __restrict__ w0, const float* __restrict__ w1,
            unsigned* __restrict__ Rh, unsigned* __restrict__ Rl) {
    int px = blockIdx.x * 256 + threadIdx.x;
    int b = blockIdx.y;
    int x = px % WW, y = px / WW;
    const float* a0 = w0 + (size_t)b * 32 * HW + px;
    float a[32];
    #pragma unroll
    for (int c = 0; c < 32; ++c) a[c] = a0[(size_t)c * HW];
    const float* bb = w1 + (size_t)b * 32 * HW;
    size_t r0 = ((size_t)b * HW + px) * 80;
    size_t r1 = ((size_t)(b + 8) * HW + px) * 80;
    unsigned hbuf[4], lbuf[4];
    int slot = 0, wpos = 32;
    float sprev = 0.f;
    int d = 0;
    #pragma unroll 1
    for (int dy = -4; dy <= 4; ++dy) {
        int yy = y + dy;
        #pragma unroll 1
        for (int dx = -4; dx <= 4; ++dx) {
            int xx = x + dx;
            float s = 0.f;
            if ((unsigned)yy < HH && (unsigned)xx < WW) {
                const float* bp = bb + yy * WW + xx;
                #pragma unroll
                for (int c = 0; c < 32; ++c) s = fmaf(a[c], bp[(size_t)c * HW], s);
                s *= (1.f / 32.f);
            }
            s = (s >= 0.f) ? s : 0.1f * s;
            if (d & 1) {
                pack_pair(sprev, s, hbuf[slot], lbuf[slot]);
                if (++slot == 4) {
                    uint4 hv = make_uint4(hbuf[0], hbuf[1], hbuf[2], hbuf[3]);
                    uint4 lv = make_uint4(lbuf[0], lbuf[1], lbuf[2], lbuf[3]);
                    *(uint4*)(Rh + r0 + wpos) = hv; *(uint4*)(Rh + r1 + wpos) = hv;
                    *(uint4*)(Rl + r0 + wpos) = lv; *(uint4*)(Rl + r1 + wpos) = lv;
                    wpos += 4; slot = 0;
                }
            } else sprev = s;
            ++d;
        }
    }
    // last value (d=80) + zero pad to word 80
    float tail = sprev;
    while (wpos < 80) {
        pack_pair(tail, 0.f, hbuf[slot], lbuf[slot]);
        tail = 0.f;
        if (++slot == 4) {
            uint4 hv = make_uint4(hbuf[0], hbuf[1], hbuf[2], hbuf[3]);
            uint4 lv = make_uint4(lbuf[0], lbuf[1], lbuf[2], lbuf[3]);
            *(uint4*)(Rh + r0 + wpos) = hv; *(uint4*)(Rh + r1 + wpos) = hv;
            *(uint4*)(Rl + r0 + wpos) = lv; *(uint4*)(Rl + r1 + wpos) = lv;
            wpos += 4; slot = 0;
        }
    }
}
// weight prep: fp32 [oc][cin][9] -> bf16 [ch][tap][hf][oc][16k]
__global__ void prep_w_kernel(const float* __restrict__ Wt, int OC, int CIN, int nch,
                              __nv_bfloat16* __restrict__ dst) {
    int n = nch * 9 * 2 * OC * 16;
    int e = blockIdx.x * 256 + threadIdx.x;
    if (e >= n) return;
    int k = e & 15, r = e >> 4;
    int oc = r % OC; r /= OC;
    int hf = r & 1; r >>= 1;
    int tap = r % 9, ch = r / 9;
    int cin = ch * 16 + k;
    float w = (cin < CIN) ? Wt[((size_t)oc * CIN + cin) * 9 + tap] : 0.f;
    __nv_bfloat16 h = __float2bfloat16(w);
    dst[e] = hf ? __float2bfloat16(w - __bfloat162float(h)) : h;
}

// ---------------- HMMA conv v3: pixel-record I/O, cp.async.16B staging ----------------
#define NHALO 396
#define SA_HF 3168
#define SA_BUF 6336
#define SW_OFF 12672

template<int OC, int ACT>
__global__ void __launch_bounds__(256, 2)
convM(const unsigned* __restrict__ Rh, const unsigned* __restrict__ Rl,
      int rstride, int nch, const __nv_bfloat16* __restrict__ wprep,
      unsigned* __restrict__ outH, unsigned* __restrict__ outL) {
    constexpr int NT = OC / 8, ORS = OC / 2;
    extern __shared__ unsigned smem[];
    const int tid = threadIdx.x, lane = tid & 31, wid = tid >> 5;
    const int gid = lane >> 2, tig = lane & 3;
    const int x0 = blockIdx.x * 64, y0 = blockIdx.y * 4, b = blockIdx.z;
    const uint32_t sab = smem_u32(smem);
    const uint32_t swb = sab + SW_OFF * 4;
    unsigned* sWp = smem + SW_OFF;

    auto issue_acts = [&](int ch, int buf) {
        uint32_t bbase = sab + (uint32_t)buf * SA_BUF * 4;
        #pragma unroll
        for (int s = 0; s < 2; ++s) {
            int j = tid + s * 256;
            if (j < NHALO) {
                int row = j / 66, col = j - row * 66;
                int gy = y0 - 1 + row, gx = x0 - 1 + col;
                bool inb = ((unsigned)gy < HH) && ((unsigned)gx < WW);
                size_t px = inb ? (size_t)(gy * WW + gx) : 0;
                int sz = inb ? 16 : 0;
                const unsigned* sh = Rh + ((size_t)b * HW + px) * rstride + ch * 8;
                const unsigned* sl = Rl + ((size_t)b * HW + px) * rstride + ch * 8;
                unsigned p = (j >> 2) & 1;
                uint32_t d0 = bbase + (unsigned)(j * 8 + p * 4) * 4;
                uint32_t d1 = bbase + (unsigned)(j * 8 + (p ^ 1) * 4) * 4;
                cp16z(d0, sh, sz);
                cp16z(d1, sh + 4, sz);
                cp16z(d0 + SA_HF * 4, sl, sz);
                cp16z(d1 + SA_HF * 4, sl + 4, sz);
            }
        }
    };
    auto issue_wts = [&](int ch) {
        const uint4* wg = (const uint4*)(wprep + (size_t)ch * 9 * 2 * OC * 16);
        const int n16 = 9 * 2 * OC * 2;
        for (int i = tid; i < n16; i += 256) cp16(swb + (uint32_t)i * 16, wg + i);
    };

    float acc[NT][2][4];
    #pragma unroll
    for (int nt = 0; nt < NT; ++nt)
        #pragma unroll
        for (int m = 0; m < 2; ++m)
            #pragma unroll
            for (int q = 0; q < 4; ++q) acc[nt][m][q] = 0.f;

    issue_acts(0, 0);
    issue_wts(0);
    CP_COMMIT();
    CP_WAIT0();
    __syncthreads();

    int buf = 0;
    for (int ch = 0; ch < nch; ++ch) {
        if (ch + 1 < nch) { issue_acts(ch + 1, buf ^ 1); CP_COMMIT(); }

        uint32_t hb = sab + (uint32_t)buf * SA_BUF * 4;
        #pragma unroll 1
        for (int tap = 0; tap < 9; ++tap) {
            int dy = tap / 3, dx = tap - dy * 3;
            unsigned ah[2][4], al[2][4];
            #pragma unroll
            for (int m = 0; m < 2; ++m) {
                int p0 = wid * 32 + m * 16;
                int prow = p0 >> 6, pcol = p0 & 63;
                int px = (prow + dy) * 66 + (pcol + dx) + (lane & 15);
                unsigned a16 = ((unsigned)px << 1) + ((unsigned)(lane >> 4) ^ ((px >> 2) & 1));
                ldmatrix_x4(ah[m], hb + (a16 << 4));
                ldmatrix_x4(al[m], hb + SA_HF * 4 + (a16 << 4));
            }
            #pragma unroll
            for (int nt = 0; nt < NT; ++nt) {
                int oc = nt * 8 + gid;
                int whb = tap * OC * 16 + oc * 8;
                unsigned b0h = sWp[whb + tig],          b1h = sWp[whb + tig + 4];
                unsigned b0l = sWp[whb + OC * 8 + tig], b1l = sWp[whb + OC * 8 + tig + 4];
                #pragma unroll
                for (int m = 0; m < 2; ++m) {
                    mma16816(acc[nt][m], ah[m], b0h, b1h);
                    mma16816(acc[nt][m], ah[m], b0l, b1l);
                    mma16816(acc[nt][m], al[m], b0h, b1h);
                }
            }
        }
        __syncthreads();
        if (ch + 1 < nch) { issue_wts(ch + 1); CP_COMMIT(); }
        CP_WAIT0();
        __syncthreads();
        buf ^= 1;
    }

    // epilogue: smem transpose to pixel-records, then coalesced STG.128
    __syncthreads();
    #pragma unroll
    for (int nt = 0; nt < NT; ++nt) {
        int ocp = nt * 4 + tig;
        #pragma unroll
        for (int m = 0; m < 2; ++m) {
            int p0 = wid * 32 + m * 16;
            int pxA = p0 + gid, pxB = pxA + 8;
            float v00 = acc[nt][m][0], v01 = acc[nt][m][1];
            float v10 = acc[nt][m][2], v11 = acc[nt][m][3];
            if (ACT) {
                v00 = (v00 >= 0.f) ? v00 : 0.1f * v00;
                v01 = (v01 >= 0.f) ? v01 : 0.1f * v01;
                v10 = (v10 >= 0.f) ? v10 : 0.1f * v10;
                v11 = (v11 >= 0.f) ? v11 : 0.1f * v11;
            }
            unsigned hp, lp;
            pack_pair(v00, v01, hp, lp);
            smem[pxA * ORS + ocp] = hp;
            smem[256 * ORS + pxA * ORS + ocp] = lp;
            pack_pair(v10, v11, hp, lp);
            smem[pxB * ORS + ocp] = hp;
            smem[256 * ORS + pxB * ORS + ocp] = lp;
        }
    }
    __syncthreads();
    const int W = 256 * ORS * 2;
    for (int i = tid * 4; i < W; i += 1024) {
        uint4 v = *(uint4*)(smem + i);
        int hf = (i >= 256 * ORS);
        int ii = i - hf * 256 * ORS;
        int pxl = ii / ORS, w = ii - pxl * ORS;
        int gy = y0 + (pxl >> 6), gx = x0 + (pxl & 63);
        unsigned* dst = (hf ? outL : outH) + ((size_t)b * HW + (size_t)(gy * WW + gx)) * ORS + w;
        *(uint4*)dst = v;
    }
}

// ---------- conv7: 16 -> 2 from 8-word records, residual + leaky, both branches ----------
__global__ void __launch_bounds__(256)
conv7_kernel(const unsigned* __restrict__ inh, const unsigned* __restrict__ inl,
             const float* __restrict__ w,
             const float* __restrict__ biflow, float* __restrict__ out) {
    __shared__ float sw[288];
    int t = threadIdx.x;
    for (int i = t; i < 288; i += 256) sw[i] = w[i];
    __syncthreads();
    int idx = blockIdx.x * 256 + t;
    if (idx >= 16 * HW) return;
    int px = idx % HW, b = idx / HW;
    int rc = (b >= 8) ? 2 : 0, ob = b & 7;
    int x = px % WW, y = px / WW;
    float a0 = 0.f, a1 = 0.f;
    #pragma unroll
    for (int ky = 0; ky < 3; ++ky) {
        int yy = y + ky - 1;
        if ((unsigned)yy >= HH) continue;
        #pragma unroll
        for (int kx = 0; kx < 3; ++kx) {
            int xx = x + kx - 1;
            if ((unsigned)xx >= WW) continue;
            int k = ky * 3 + kx;
            size_t base = ((size_t)b * HW + (size_t)(yy * WW + xx)) * 8;
            uint4 H0 = *(const uint4*)(inh + base), H1 = *(const uint4*)(inh + base + 4);
            uint4 L0 = *(const uint4*)(inl + base), L1 = *(const uint4*)(inl + base + 4);
            unsigned hwv[8] = {H0.x, H0.y, H0.z, H0.w, H1.x, H1.y, H1.z, H1.w};
            unsigned lwv[8] = {L0.x, L0.y, L0.z, L0.w, L1.x, L1.y, L1.z, L1.w};
            #pragma unroll
            for (int j = 0; j < 8; ++j) {
                float v0 = __uint_as_float(hwv[j] << 16) + __uint_as_float(lwv[j] << 16);
                float v1 = __uint_as_float(hwv[j] & 0xffff0000u) + __uint_as_float(lwv[j] & 0xffff0000u);
                a0 = fmaf(v0, sw[(2 * j) * 9 + k], a0);
                a0 = fmaf(v1, sw[(2 * j + 1) * 9 + k], a0);
                a1 = fmaf(v0, sw[144 + (2 * j) * 9 + k], a1);
                a1 = fmaf(v1, sw[144 + (2 * j + 1) * 9 + k], a1);
            }
        }
    }
    a0 = (a0 >= 0.f) ? a0 : 0.1f * a0;
    a1 = (a1 >= 0.f) ? a1 : 0.1f * a1;
    size_t o = ((size_t)ob * 4 + rc) * HW + px;
    out[o]      = a0 + biflow[o];
    out[o + HW] = a1 + biflow[o + HW];
}

// ---------------- launch ----------------
extern "C" void kernel_launch(void* const* d_in, const int* in_sizes, int n_in,
                              void* d_out, int out_size) {
    const float* f0 = (const float*)d_in[0];
    const float* f1 = (const float*)d_in[1];
    const float* bfp = (const float*)d_in[2];
    const float* ft = (const float*)d_in[3];
    const float* bt = (const float*)d_in[4];
    const float* Wt[7] = {(const float*)d_in[5], (const float*)d_in[6], (const float*)d_in[7],
                          (const float*)d_in[8], (const float*)d_in[9], (const float*)d_in[10],
                          (const float*)d_in[11]};
    float* out = (float*)d_out;

    float *biflow, *accA, *accB, *w0, *w1;
    unsigned *R1h, *R1l, *h1h, *h1l, *h2h, *h2l, *h6h, *h6l;
    __nv_bfloat16* wp;
    cudaGetSymbolAddress((void**)&biflow, g_biflow);
    cudaGetSymbolAddress((void**)&accA, g_accA);
    cudaGetSymbolAddress((void**)&accB, g_accB);
    cudaGetSymbolAddress((void**)&w0, g_warp0);
    cudaGetSymbolAddress((void**)&w1, g_warp1);
    cudaGetSymbolAddress((void**)&R1h, g_R1h); cudaGetSymbolAddress((void**)&R1l, g_R1l);
    cudaGetSymbolAddress((void**)&h1h, g_h1h); cudaGetSymbolAddress((void**)&h1l, g_h1l);
    cudaGetSymbolAddress((void**)&h2h, g_h2h); cudaGetSymbolAddress((void**)&h2l, g_h2l);
    cudaGetSymbolAddress((void**)&h6h, g_h6h); cudaGetSymbolAddress((void**)&h6l, g_h6l);
    cudaGetSymbolAddress((void**)&wp, g_wprep);

    const int SM64 = (SW_OFF + 9 * 2 * 64 * 8) * 4;   // 87552
    const int SM32 = (SW_OFF + 9 * 2 * 32 * 8) * 4;   // 69120
    const int SM16 = (SW_OFF + 9 * 2 * 16 * 8) * 4;   // 59904
    static bool attr = false;
    if (!attr) {
        cudaFuncSetAttribute(convM<64,0>, cudaFuncAttributeMaxDynamicSharedMemorySize, SM64);
        cudaFuncSetAttribute(convM<64,1>, cudaFuncAttributeMaxDynamicSharedMemorySize, SM64);
        cudaFuncSetAttribute(convM<32,0>, cudaFuncAttributeMaxDynamicSharedMemorySize, SM32);
        cudaFuncSetAttribute(convM<16,0>, cudaFuncAttributeMaxDynamicSharedMemorySize, SM16);
        attr = true;
    }

    // front-end
    {
        int n = BB * 4 * HW;
        upsample_kernel<<<(n + 255) / 256, 256>>>(bfp, biflow);
        n = BB * 33 * HW;
        zero2_kernel<<<(n + 255) / 256, 256>>>(accA, accB, n);
        dim3 gs((BB * HW + 255) / 256, 2);
        splatM_kernel<<<gs, 256>>>(f0, f1, biflow, accA, accB);
        normM_kernel<<<gs, 256>>>(accA, accB, w0, w1, R1h, R1l);
        packM_kernel<<<gs, 256>>>(ft, bt, R1h, R1l);
        dim3 gcr(HW / 256, BB);
        corr_kernel<<<gcr, 256>>>(w0, w1, R1h, R1l);
    }
    // weight prep
    const int O1 = 0, O2 = 184320, O3 = 258048, O4 = 331776, O5 = 368640, O6 = 387072;
    {
        int n1 = 10 * 288 * 64;
        prep_w_kernel<<<(n1 + 255) / 256, 256>>>(Wt[0], 64, 145, 10, wp + O1);
        int n2 = 4 * 288 * 64;
        prep_w_kernel<<<(n2 + 255) / 256, 256>>>(Wt[1], 64, 64, 4, wp + O2);
        prep_w_kernel<<<(n2 + 255) / 256, 256>>>(Wt[2], 64, 64, 4, wp + O3);
        int n4 = 4 * 288 * 32;
        prep_w_kernel<<<(n4 + 255) / 256, 256>>>(Wt[3], 32, 64, 4, wp + O4);
        int n5 = 2 * 288 * 32;
        prep_w_kernel<<<(n5 + 255) / 256, 256>>>(Wt[4], 32, 32, 2, wp + O5);
        int n6 = 2 * 288 * 16;
        prep_w_kernel<<<(n6 + 255) / 256, 256>>>(Wt[5], 16, 32, 2, wp + O6);
    }

    // conv stack, both branches fused (gridZ = 16)
    dim3 gc(WW / 64, HH / 4, 16);
    convM<64,0><<<gc, 256, SM64>>>(R1h, R1l, 80, 10, wp + O1, h1h, h1l);
    convM<64,0><<<gc, 256, SM64>>>(h1h, h1l, 32, 4, wp + O2, h2h, h2l);
    convM<64,1><<<gc, 256, SM64>>>(h2h, h2l, 32, 4, wp + O3, h1h, h1l);
    convM<32,0><<<gc, 256, SM32>>>(h1h, h1l, 32, 4, wp + O4, h2h, h2l);
    convM<32,0><<<gc, 256, SM32>>>(h2h, h2l, 16, 2, wp + O5, h1h, h1l);
    convM<16,0><<<gc, 256, SM16>>>(h1h, h1l, 16, 2, wp + O6, h6h, h6l);
    int n7 = 16 * HW;
    conv7_kernel<<<(n7 + 255) / 256, 256>>>(h6h, h6l, Wt[6], biflow, out);
}